// round 11
// baseline (speedup 1.0000x reference)
#include <cuda_runtime.h>
#include <cuda_fp16.h>
#include <math.h>

#define SEQ 4096
#define INP 457
#define EMB 2048
#define G4E 8192
#define G4I 1828
#define NCTA 148
#define DCLUST 8
#define CROWS 52   // fp16 Whh rows cached in SMEM per encoder CTA
#define DROWS 116  // fp32 W_eff rows cached in SMEM per decoder CTA
#define DPAD 460   // padded row stride for decoder SMEM

__device__ float g_gx[(size_t)SEQ * G4E];     // Wih@x + biases, per timestep
__device__ float g_wihT[(size_t)INP * G4E];   // enc_Wih transposed
__device__ __half g_whh_h[(size_t)G4E * EMB]; // enc_Whh in fp16
__device__ float g_weff[(size_t)G4I * INP];   // (dec_Wih+dec_Whh)@dec_Whr
__device__ float g_g0[G4I];                   // decoder step-0 gates
__device__ float g_h[EMB];                    // final encoder hidden (for dec_g0)
__device__ float g_henc[2][EMB];              // encoder hidden, double-buffered
__device__ volatile unsigned g_arr_enc[NCTA * 32]; // one 128B line per CTA

__device__ __forceinline__ float sigf(float x) { return 1.0f / (1.0f + expf(-x)); }

__device__ __forceinline__ unsigned smem_u32(const void* p) {
  unsigned a;
  asm("{ .reg .u64 t; cvta.to.shared.u64 t, %1; cvt.u32.u64 %0, t; }" : "=r"(a) : "l"(p));
  return a;
}

// fp16 conversion of enc_Whh + flag/h0 init (fused, launch #0).
__global__ void conv_init_kernel(const float* __restrict__ whh) {
  size_t i = (size_t)blockIdx.x * blockDim.x + threadIdx.x;
  size_t i4 = i * 4;
  float4 v = *(const float4*)(whh + i4);
  __half2* dst = (__half2*)(g_whh_h + i4);
  dst[0] = __floats2half2_rn(v.x, v.y);
  dst[1] = __floats2half2_rn(v.z, v.w);
  if (i < NCTA * 32) g_arr_enc[i] = 1u;   // h_0 considered published
  if (i < EMB) g_henc[0][i] = 0.0f;       // h_0 = 0 in parity-0 buffer
}

// Transpose enc_Wih [8192][457] -> g_wihT [457][8192]
__global__ void tr_kernel(const float* __restrict__ in) {
  __shared__ float tile[32][33];
  int r0 = blockIdx.x * 32, c0 = blockIdx.y * 32;
  int x = threadIdx.x;
  for (int y = threadIdx.y; y < 32; y += 8) {
    int c = c0 + x;
    if (c < INP) tile[y][x] = in[(size_t)(r0 + y) * INP + c];
  }
  __syncthreads();
  for (int y = threadIdx.y; y < 32; y += 8) {
    int c = c0 + y;
    if (c < INP) g_wihT[(size_t)c * G4E + r0 + x] = tile[x][y];
  }
}

// Gx[t][r] = sum_k x[t][k]*Wih[r][k] + bih[r] + bhh[r]
__global__ void __launch_bounds__(256) gx_kernel(const float* __restrict__ x,
                                                 const float* __restrict__ bih,
                                                 const float* __restrict__ bhh) {
  __shared__ float xs[INP * 20];
  const int tid = threadIdx.x;
  const int rb = blockIdx.x * 256, tb = blockIdx.y * 16;
  for (int i = tid; i < 16 * INP; i += 256) {
    int tt = i / INP, k = i - tt * INP;
    xs[k * 20 + tt] = x[(size_t)(tb + tt) * INP + k];
  }
  __syncthreads();
  const int r = rb + tid;
  float acc[16];
#pragma unroll
  for (int j = 0; j < 16; j++) acc[j] = 0.0f;
  for (int k = 0; k < INP; k++) {
    float w = g_wihT[(size_t)k * G4E + r];
    const float4* xv = (const float4*)(xs + k * 20);
    float4 a = xv[0], b = xv[1], c = xv[2], d = xv[3];
    acc[0]  += w * a.x; acc[1]  += w * a.y; acc[2]  += w * a.z; acc[3]  += w * a.w;
    acc[4]  += w * b.x; acc[5]  += w * b.y; acc[6]  += w * b.z; acc[7]  += w * b.w;
    acc[8]  += w * c.x; acc[9]  += w * c.y; acc[10] += w * c.z; acc[11] += w * c.w;
    acc[12] += w * d.x; acc[13] += w * d.y; acc[14] += w * d.z; acc[15] += w * d.w;
  }
  float bsum = bih[r] + bhh[r];
#pragma unroll
  for (int j = 0; j < 16; j++) g_gx[(size_t)(tb + j) * G4E + r] = acc[j] + bsum;
}

// W_eff[r][j] = sum_m (dWih[r][m]+dWhh[r][m]) * dWhr[m][j]
__global__ void __launch_bounds__(128) weff_kernel(const float* __restrict__ dwih,
                                                   const float* __restrict__ dwhh,
                                                   const float* __restrict__ whr) {
  __shared__ float wcs[8 * 128];
  const int tid = threadIdx.x;
  const int r0 = blockIdx.x * 8;
  float acc[8][4];
#pragma unroll
  for (int i = 0; i < 8; i++)
#pragma unroll
    for (int j = 0; j < 4; j++) acc[i][j] = 0.0f;

  for (int kb = 0; kb < EMB; kb += 128) {
    __syncthreads();
#pragma unroll
    for (int i = 0; i < 8; i++) {
      int row = r0 + i; if (row > G4I - 1) row = G4I - 1;
      size_t idx = (size_t)row * EMB + kb + tid;
      wcs[i * 128 + tid] = dwih[idx] + dwhh[idx];
    }
    __syncthreads();
#pragma unroll 4
    for (int kk = 0; kk < 128; kk++) {
      const float* wrow = whr + (size_t)(kb + kk) * INP;
      float v0 = wrow[tid];
      float v1 = wrow[tid + 128];
      float v2 = wrow[tid + 256];
      float v3 = (tid < 73) ? wrow[tid + 384] : 0.0f;
#pragma unroll
      for (int i = 0; i < 8; i++) {
        float w = wcs[i * 128 + kk];
        acc[i][0] += w * v0; acc[i][1] += w * v1;
        acc[i][2] += w * v2; acc[i][3] += w * v3;
      }
    }
  }
#pragma unroll
  for (int i = 0; i < 8; i++) {
    int row = r0 + i;
    if (row < G4I) {
      size_t rb = (size_t)row * INP;
      g_weff[rb + tid]       = acc[i][0];
      g_weff[rb + tid + 128] = acc[i][1];
      g_weff[rb + tid + 256] = acc[i][2];
      if (tid < 73) g_weff[rb + tid + 384] = acc[i][3];
    }
  }
}

// Persistent encoder, fp16 weights, R8-style flag exchange + h in registers.
extern __shared__ __half esmh[];
__global__ void __launch_bounds__(256, 1) enc_kernel(const float* __restrict__ whhf) {
  __shared__ float gsum[64];
  const int tid = threadIdx.x, wid = tid >> 5, lane = tid & 31, b = blockIdx.x;
  const int cnt   = (b < 124) ? 14 : 13;
  const int start = (b < 124) ? 14 * b : 1736 + 13 * (b - 124);
  const int nrows = 4 * cnt;
  __half* ws = esmh;                                   // CROWS * 2048 halfs
  float*  hs = (float*)(esmh + (size_t)CROWS * EMB);   // 2048 floats (staging)
  float4* hs4 = (float4*)hs;

  for (int idx = tid; idx < CROWS * EMB; idx += 256) {
    int i = idx >> 11, k = idx & 2047;
    int e = start + (i >> 2), q = i & 3;
    ws[idx] = g_whh_h[((size_t)(q << 11) + e) * EMB + k];
  }
  __syncthreads();

  float c = 0.0f;
  for (int t = 0; t < SEQ; t++) {
    float gx0 = 0.f, gx1 = 0.f, gx2 = 0.f, gx3 = 0.f;
    if (tid < cnt) {
      size_t base = (size_t)t * G4E + start + tid;
      gx0 = __ldcg(&g_gx[base]);
      gx1 = __ldcg(&g_gx[base + 2048]);
      gx2 = __ldcg(&g_gx[base + 4096]);
      gx3 = __ldcg(&g_gx[base + 6144]);
    }
    // Wait for all CTAs to have published h_t, then stage h into SMEM.
    if (tid < NCTA) {
      while (g_arr_enc[tid * 32] < (unsigned)(t + 1)) {}
      __threadfence();
    }
    __syncthreads();
    const float4* h4g = (const float4*)g_henc[t & 1];
    for (int i = tid; i < EMB / 4; i += 256) hs4[i] = __ldcg(h4g + i);
    __syncthreads();
    float4 h4[16];
#pragma unroll
    for (int j = 0; j < 16; j++) h4[j] = hs4[lane + 32 * j];

#pragma unroll 1
    for (int k = 0; k < 7; k++) {
      int i = wid + 8 * k;
      if (i >= nrows) break;  // warp-uniform
      float sum = 0.0f;
      if (i < CROWS) {
        const uint2* wr = (const uint2*)(ws + (size_t)i * EMB);
#pragma unroll
        for (int j = 0; j < 16; j++) {
          uint2 wp = wr[lane + 32 * j];
          float2 a = __half22float2(*(__half2*)&wp.x);
          float2 bq = __half22float2(*(__half2*)&wp.y);
          float4 hv = h4[j];
          sum += a.x * hv.x; sum += a.y * hv.y;
          sum += bq.x * hv.z; sum += bq.y * hv.w;
        }
      } else {
        int e = start + (i >> 2), q = i & 3;
        const uint2* wr = (const uint2*)(g_whh_h + ((size_t)(q << 11) + e) * EMB);
#pragma unroll
        for (int j = 0; j < 16; j++) {
          uint2 wp = __ldcg(wr + lane + 32 * j);
          float2 a = __half22float2(*(__half2*)&wp.x);
          float2 bq = __half22float2(*(__half2*)&wp.y);
          float4 hv = h4[j];
          sum += a.x * hv.x; sum += a.y * hv.y;
          sum += bq.x * hv.z; sum += bq.y * hv.w;
        }
      }
#pragma unroll
      for (int o = 16; o; o >>= 1) sum += __shfl_xor_sync(0xffffffffu, sum, o);
      if (lane == 0) gsum[i] = sum;
    }
    __syncthreads();

    if (tid < cnt) {
      float gi = gsum[4 * tid + 0] + gx0;
      float gf = gsum[4 * tid + 1] + gx1;
      float gg = gsum[4 * tid + 2] + gx2;
      float go = gsum[4 * tid + 3] + gx3;
      c = sigf(gf) * c + sigf(gi) * tanhf(gg);
      float hnew = sigf(go) * tanhf(c);
      g_henc[(t + 1) & 1][start + tid] = hnew;
      if (t == SEQ - 1) g_h[start + tid] = hnew;
    }
    __syncthreads();
    if (tid == 0) { __threadfence(); g_arr_enc[b * 32] = (unsigned)(t + 2); }
  }
}

// g0[r] = dec_Wih[r] . h_enc + bih[r] + bhh[r]
__global__ void dec_g0_kernel(const float* __restrict__ dwih,
                              const float* __restrict__ bih,
                              const float* __restrict__ bhh) {
  int wid = threadIdx.x >> 5, lane = threadIdx.x & 31;
  int row = blockIdx.x * 8 + wid;
  if (row >= G4I) return;
  const float4* w = (const float4*)(dwih + (size_t)row * EMB);
  const float4* h = (const float4*)g_h;
  float sum = 0.0f;
  for (int k = lane; k < EMB / 4; k += 32) {
    float4 a = w[k], b = h[k];
    sum += a.x * b.x + a.y * b.y + a.z * b.z + a.w * b.w;
  }
#pragma unroll
  for (int o = 16; o; o >>= 1) sum += __shfl_xor_sync(0xffffffffu, sum, o);
  if (lane == 0) g_g0[row] = sum + bih[row] + bhh[row];
}

// Cluster decoder: ONE cluster of 8 CTAs. CTA r owns elems [57r, 57r+cnt),
// cnt=57 (58 for r=7), nrows=4*cnt. Rows l<DROWS in SMEM (fp32), rest from L2.
// h_raw exchanged via DSMEM mailboxes + one cluster barrier per step.
__global__ void __cluster_dims__(DCLUST, 1, 1) __launch_bounds__(256, 1)
dec_kernel(const float* __restrict__ bih, const float* __restrict__ bhh,
           float* __restrict__ out) {
  float* ws   = (float*)esmh;            // DROWS * DPAD
  float* hrs  = ws + DROWS * DPAD;       // DPAD
  float* mail = hrs + DPAD;              // 2 * 64 (own chunk, double-buffered)
  float* bs   = mail + 128;              // 240
  float* gsum = bs + 240;                // 240
  const int tid = threadIdx.x, wid = tid >> 5, lane = tid & 31;
  const int r = blockIdx.x;
  const int cnt = (r < 7) ? 57 : 58;
  const int e0 = 57 * r;
  const int nrows = 4 * cnt;

  for (int idx = tid; idx < DROWS * INP; idx += 256) {
    int l = idx / INP, k = idx - l * INP;
    int q = l & 3, el = l >> 2;
    ws[l * DPAD + k] = g_weff[(size_t)(q * INP + e0 + el) * INP + k];
  }
  if (tid < nrows) {
    int q = tid & 3, el = tid >> 2;
    bs[tid] = bih[q * INP + e0 + el] + bhh[q * INP + e0 + el];
  }
  __syncthreads();

  float c = 0.0f;
  for (int t = 0; t < SEQ; t++) {
    const int par = t & 1;
    if (t > 0) {
      // Gather all ranks' h_raw chunks via DSMEM.
      for (int i = tid; i < 464; i += 256) {
        int rr = i / 58, j = i - rr * 58;
        if (rr < 7 && j >= 57) continue;
        int e = (rr < 7) ? 57 * rr + j : 399 + j;
        unsigned la = smem_u32(&mail[par * 64 + j]);
        unsigned ra;
        asm("mapa.shared::cluster.u32 %0, %1, %2;" : "=r"(ra) : "r"(la), "r"(rr));
        float v;
        asm volatile("ld.shared::cluster.f32 %0, [%1];" : "=f"(v) : "r"(ra));
        hrs[e] = v;
      }
      __syncthreads();
#pragma unroll 1
      for (int k8 = 0; k8 < 29; k8++) {
        int l = wid + 8 * k8;
        if (l < nrows) {
          float sum = 0.0f;
          if (l < DROWS) {
            const float* p = ws + l * DPAD;
#pragma unroll 5
            for (int k = lane; k < INP; k += 32) sum += p[k] * hrs[k];
          } else {
            int q = l & 3, el = l >> 2;
            const float* p = g_weff + (size_t)(q * INP + e0 + el) * INP;
#pragma unroll 5
            for (int k = lane; k < INP; k += 32) sum += __ldcg(p + k) * hrs[k];
          }
#pragma unroll
          for (int o = 16; o; o >>= 1) sum += __shfl_xor_sync(0xffffffffu, sum, o);
          if (lane == 0) gsum[l] = sum;
        }
      }
      __syncthreads();
    }
    if (tid < cnt) {
      int e = e0 + tid;
      float gi, gf, gg, go;
      if (t == 0) {
        gi = g_g0[e]; gf = g_g0[INP + e]; gg = g_g0[2 * INP + e]; go = g_g0[3 * INP + e];
      } else {
        gi = gsum[4 * tid + 0] + bs[4 * tid + 0];
        gf = gsum[4 * tid + 1] + bs[4 * tid + 1];
        gg = gsum[4 * tid + 2] + bs[4 * tid + 2];
        go = gsum[4 * tid + 3] + bs[4 * tid + 3];
      }
      c = sigf(gf) * c + sigf(gi) * tanhf(gg);
      out[(size_t)(SEQ - 1 - t) * INP + e] = c;
      mail[(par ^ 1) * 64 + tid] = sigf(go) * tanhf(c);
    }
    // One cluster barrier per step: orders mail writes before peers' reads.
    asm volatile("barrier.cluster.arrive.aligned;" ::: "memory");
    asm volatile("barrier.cluster.wait.aligned;" ::: "memory");
  }
}

// In-place row softmax over out[4096][457]
__global__ void softmax_kernel(float* __restrict__ out) {
  __shared__ float red[32];
  const int t = blockIdx.x, tid = threadIdx.x, lane = tid & 31, wid = tid >> 5;
  float v = (tid < INP) ? out[(size_t)t * INP + tid] : -1e30f;
  float m = v;
#pragma unroll
  for (int o = 16; o; o >>= 1) m = fmaxf(m, __shfl_xor_sync(0xffffffffu, m, o));
  if (lane == 0) red[wid] = m;
  __syncthreads();
  m = -1e30f;
  for (int i = 0; i < 16; i++) m = fmaxf(m, red[i]);
  __syncthreads();
  float e = (tid < INP) ? expf(v - m) : 0.0f;
  float sum = e;
#pragma unroll
  for (int o = 16; o; o >>= 1) sum += __shfl_xor_sync(0xffffffffu, sum, o);
  if (lane == 0) red[wid] = sum;
  __syncthreads();
  sum = 0.0f;
  for (int i = 0; i < 16; i++) sum += red[i];
  if (tid < INP) out[(size_t)t * INP + tid] = e / sum;
}

extern "C" void kernel_launch(void* const* d_in, const int* in_sizes, int n_in,
                              void* d_out, int out_size) {
  const float* x    = (const float*)d_in[0];
  const float* eWih = (const float*)d_in[1];
  const float* eWhh = (const float*)d_in[2];
  const float* ebih = (const float*)d_in[3];
  const float* ebhh = (const float*)d_in[4];
  const float* dWih = (const float*)d_in[5];
  const float* dWhh = (const float*)d_in[6];
  const float* dbih = (const float*)d_in[7];
  const float* dbhh = (const float*)d_in[8];
  const float* dWhr = (const float*)d_in[9];
  float* out = (float*)d_out;

  const int enc_smem = CROWS * EMB * 2 + EMB * 4;                       // 221,184 B
  const int dec_smem = (DROWS * DPAD + DPAD + 128 + 240 + 240) * 4;     // 217,712 B
  cudaFuncSetAttribute(enc_kernel, cudaFuncAttributeMaxDynamicSharedMemorySize, enc_smem);
  cudaFuncSetAttribute(dec_kernel, cudaFuncAttributeMaxDynamicSharedMemorySize, dec_smem);

  conv_init_kernel<<<16384, 256>>>(eWhh);
  tr_kernel<<<dim3(256, 15), dim3(32, 8)>>>(eWih);
  gx_kernel<<<dim3(32, 256), 256>>>(x, ebih, ebhh);
  enc_kernel<<<NCTA, 256, enc_smem>>>(eWhh);
  weff_kernel<<<229, 128>>>(dWih, dWhh, dWhr);
  dec_g0_kernel<<<229, 256>>>(dWih, dbih, dbhh);
  dec_kernel<<<DCLUST, 256, dec_smem>>>(dbih, dbhh, out);
  softmax_kernel<<<SEQ, 512>>>(out);
}

// round 12
// speedup vs baseline: 2.5092x; 2.5092x over previous
#include <cuda_runtime.h>
#include <cuda_fp16.h>
#include <math.h>
#include <string.h>

#define SEQ 4096
#define INP 457
#define EMB 2048
#define G4E 8192
#define G4I 1828
#define NCTA 148
#define DCTA 57
#define CROWS 52   // fp16 Whh rows cached in SMEM per encoder CTA

__device__ float g_gx[(size_t)SEQ * G4E];     // Wih@x + biases, per timestep
__device__ float g_wihT[(size_t)INP * G4E];   // enc_Wih transposed
__device__ __half g_whh_h[(size_t)G4E * EMB]; // enc_Whh in fp16
__device__ float g_weff[(size_t)G4I * INP];   // (dec_Wih+dec_Whh)@dec_Whr
__device__ float g_g0[G4I];                   // decoder step-0 gates
__device__ float g_h[EMB];                    // final encoder hidden (fp32, for dec_g0)
__device__ __half g_hench[2][EMB];            // encoder hidden fp16, double-buffered
__device__ float g_hraw[2 * INP];             // decoder raw hidden, double-buffered
__device__ volatile unsigned g_arr_enc[NCTA * 32];  // one 128B line per CTA
__device__ volatile unsigned g_arr_dec[DCTA * 32];

__device__ __forceinline__ float sigf(float x) { return 1.0f / (1.0f + expf(-x)); }

__device__ __forceinline__ __half2 u2h2(unsigned u) {
  __half2 h; memcpy(&h, &u, 4); return h;
}
__device__ __forceinline__ __half ldcg_h(const __half* p) {
  unsigned short v;
  asm volatile("ld.global.cg.u16 %0, [%1];" : "=h"(v) : "l"(p));
  __half h; memcpy(&h, &v, 2); return h;
}

// Single-handshake distributed barrier, line-padded flags (R8-proven).
__device__ __forceinline__ void dbar1(volatile unsigned* arr, unsigned s,
                                      int b, int tid, int n) {
  __threadfence();
  __syncthreads();
  if (tid == 0) arr[b * 32] = s;
  if (tid < n) { while (arr[tid * 32] < s) {} }
  __threadfence();
  __syncthreads();
}

// fp16 conversion of enc_Whh + flag/h0 init (fused, launch #0).
__global__ void conv_init_kernel(const float* __restrict__ whh) {
  size_t i = (size_t)blockIdx.x * blockDim.x + threadIdx.x;
  size_t i4 = i * 4;
  float4 v = *(const float4*)(whh + i4);
  __half2* dst = (__half2*)(g_whh_h + i4);
  dst[0] = __floats2half2_rn(v.x, v.y);
  dst[1] = __floats2half2_rn(v.z, v.w);
  if (i < NCTA * 32) g_arr_enc[i] = 1u;   // h_0 considered published
  if (i < DCTA * 32) g_arr_dec[i] = 0u;
  if (i < EMB) g_hench[0][i] = __float2half_rn(0.0f);
}

// Transpose enc_Wih [8192][457] -> g_wihT [457][8192]
__global__ void tr_kernel(const float* __restrict__ in) {
  __shared__ float tile[32][33];
  int r0 = blockIdx.x * 32, c0 = blockIdx.y * 32;
  int x = threadIdx.x;
  for (int y = threadIdx.y; y < 32; y += 8) {
    int c = c0 + x;
    if (c < INP) tile[y][x] = in[(size_t)(r0 + y) * INP + c];
  }
  __syncthreads();
  for (int y = threadIdx.y; y < 32; y += 8) {
    int c = c0 + y;
    if (c < INP) g_wihT[(size_t)c * G4E + r0 + x] = tile[x][y];
  }
}

// Gx[t][r] = sum_k x[t][k]*Wih[r][k] + bih[r] + bhh[r]
__global__ void __launch_bounds__(256) gx_kernel(const float* __restrict__ x,
                                                 const float* __restrict__ bih,
                                                 const float* __restrict__ bhh) {
  __shared__ float xs[INP * 20];
  const int tid = threadIdx.x;
  const int rb = blockIdx.x * 256, tb = blockIdx.y * 16;
  for (int i = tid; i < 16 * INP; i += 256) {
    int tt = i / INP, k = i - tt * INP;
    xs[k * 20 + tt] = x[(size_t)(tb + tt) * INP + k];
  }
  __syncthreads();
  const int r = rb + tid;
  float acc[16];
#pragma unroll
  for (int j = 0; j < 16; j++) acc[j] = 0.0f;
  for (int k = 0; k < INP; k++) {
    float w = g_wihT[(size_t)k * G4E + r];
    const float4* xv = (const float4*)(xs + k * 20);
    float4 a = xv[0], b = xv[1], c = xv[2], d = xv[3];
    acc[0]  += w * a.x; acc[1]  += w * a.y; acc[2]  += w * a.z; acc[3]  += w * a.w;
    acc[4]  += w * b.x; acc[5]  += w * b.y; acc[6]  += w * b.z; acc[7]  += w * b.w;
    acc[8]  += w * c.x; acc[9]  += w * c.y; acc[10] += w * c.z; acc[11] += w * c.w;
    acc[12] += w * d.x; acc[13] += w * d.y; acc[14] += w * d.z; acc[15] += w * d.w;
  }
  float bsum = bih[r] + bhh[r];
#pragma unroll
  for (int j = 0; j < 16; j++) g_gx[(size_t)(tb + j) * G4E + r] = acc[j] + bsum;
}

// W_eff[r][j] = sum_m (dWih[r][m]+dWhh[r][m]) * dWhr[m][j]
__global__ void __launch_bounds__(128) weff_kernel(const float* __restrict__ dwih,
                                                   const float* __restrict__ dwhh,
                                                   const float* __restrict__ whr) {
  __shared__ float wcs[8 * 128];
  const int tid = threadIdx.x;
  const int r0 = blockIdx.x * 8;
  float acc[8][4];
#pragma unroll
  for (int i = 0; i < 8; i++)
#pragma unroll
    for (int j = 0; j < 4; j++) acc[i][j] = 0.0f;

  for (int kb = 0; kb < EMB; kb += 128) {
    __syncthreads();
#pragma unroll
    for (int i = 0; i < 8; i++) {
      int row = r0 + i; if (row > G4I - 1) row = G4I - 1;
      size_t idx = (size_t)row * EMB + kb + tid;
      wcs[i * 128 + tid] = dwih[idx] + dwhh[idx];
    }
    __syncthreads();
#pragma unroll 4
    for (int kk = 0; kk < 128; kk++) {
      const float* wrow = whr + (size_t)(kb + kk) * INP;
      float v0 = wrow[tid];
      float v1 = wrow[tid + 128];
      float v2 = wrow[tid + 256];
      float v3 = (tid < 73) ? wrow[tid + 384] : 0.0f;
#pragma unroll
      for (int i = 0; i < 8; i++) {
        float w = wcs[i * 128 + kk];
        acc[i][0] += w * v0; acc[i][1] += w * v1;
        acc[i][2] += w * v2; acc[i][3] += w * v3;
      }
    }
  }
#pragma unroll
  for (int i = 0; i < 8; i++) {
    int row = r0 + i;
    if (row < G4I) {
      size_t rb = (size_t)row * INP;
      g_weff[rb + tid]       = acc[i][0];
      g_weff[rb + tid + 128] = acc[i][1];
      g_weff[rb + tid + 256] = acc[i][2];
      if (tid < 73) g_weff[rb + tid + 384] = acc[i][3];
    }
  }
}

// Persistent encoder: fp16 weights + fp16 h, HFMA2 inner loop, fused poll-read.
// CTA b owns cnt (14/13) hidden elems at start. Gate rows i = 4*el + q,
// global row q*2048 + start + el. Rows i<CROWS SMEM-resident, rest L2-streamed.
extern __shared__ __half esmh[];
__global__ void __launch_bounds__(256, 1) enc_kernel(const float* __restrict__ whhf) {
  __shared__ float gsum[64];
  const int tid = threadIdx.x, wid = tid >> 5, lane = tid & 31, b = blockIdx.x;
  const int cnt   = (b < 124) ? 14 : 13;
  const int start = (b < 124) ? 14 * b : 1736 + 13 * (b - 124);
  const int nrows = 4 * cnt;
  __half* ws  = esmh;                       // CROWS * 2048 halfs
  __half* hs2 = esmh + (size_t)CROWS * EMB; // 2048 halfs (h staging)

  for (int idx = tid; idx < CROWS * EMB; idx += 256) {
    int i = idx >> 11, k = idx & 2047;
    int e = start + (i >> 2), q = i & 3;
    ws[idx] = g_whh_h[((size_t)(q << 11) + e) * EMB + k];
  }
  __syncthreads();

  float c = 0.0f;
  for (int t = 0; t < SEQ; t++) {
    const int par = t & 1;
    float gx0 = 0.f, gx1 = 0.f, gx2 = 0.f, gx3 = 0.f;
    if (tid < cnt) {
      size_t base = (size_t)t * G4E + start + tid;
      gx0 = __ldcg(&g_gx[base]);
      gx1 = __ldcg(&g_gx[base + 2048]);
      gx2 = __ldcg(&g_gx[base + 4096]);
      gx3 = __ldcg(&g_gx[base + 6144]);
    }
    // Fused poll + chunk read: thread j waits on producer j only, then pulls
    // its fp16 chunk straight into staging (pipelines with stragglers).
    if (tid < NCTA) {
      while (g_arr_enc[tid * 32] < (unsigned)(t + 1)) {}
      __threadfence();
      int cj = (tid < 124) ? 14 : 13;
      int sj = (tid < 124) ? 14 * tid : 1736 + 13 * (tid - 124);
      const __half* src = &g_hench[par][sj];
      for (int k = 0; k < cj; k++) hs2[sj + k] = ldcg_h(src + k);
    }
    __syncthreads();

    // Lane-partition of h into registers: 8 x uint4 (64 halfs), slot j holds
    // halfs [8*(lane+32j), +8).
    uint4 hreg[8];
    const uint4* h4 = (const uint4*)hs2;
#pragma unroll
    for (int j = 0; j < 8; j++) hreg[j] = h4[lane + 32 * j];

#pragma unroll 1
    for (int k = 0; k < 7; k++) {
      int i = wid + 8 * k;
      if (i >= nrows) break;  // warp-uniform
      float sum = 0.0f;
      if (i < CROWS) {
        const uint4* wr = (const uint4*)(ws + (size_t)i * EMB);
#pragma unroll
        for (int j = 0; j < 8; j++) {
          uint4 w = wr[lane + 32 * j];
          __half2 acc = __hmul2(u2h2(w.x), u2h2(hreg[j].x));
          acc = __hfma2(u2h2(w.y), u2h2(hreg[j].y), acc);
          acc = __hfma2(u2h2(w.z), u2h2(hreg[j].z), acc);
          acc = __hfma2(u2h2(w.w), u2h2(hreg[j].w), acc);
          float2 f = __half22float2(acc);
          sum += f.x + f.y;
        }
      } else {
        int e = start + (i >> 2), q = i & 3;
        const uint4* wr = (const uint4*)(g_whh_h + ((size_t)(q << 11) + e) * EMB);
#pragma unroll
        for (int j = 0; j < 8; j++) {
          uint4 w = __ldcg(wr + lane + 32 * j);
          __half2 acc = __hmul2(u2h2(w.x), u2h2(hreg[j].x));
          acc = __hfma2(u2h2(w.y), u2h2(hreg[j].y), acc);
          acc = __hfma2(u2h2(w.z), u2h2(hreg[j].z), acc);
          acc = __hfma2(u2h2(w.w), u2h2(hreg[j].w), acc);
          float2 f = __half22float2(acc);
          sum += f.x + f.y;
        }
      }
#pragma unroll
      for (int o = 16; o; o >>= 1) sum += __shfl_xor_sync(0xffffffffu, sum, o);
      if (lane == 0) gsum[i] = sum;
    }
    __syncthreads();

    if (tid < cnt) {
      float gi = gsum[4 * tid + 0] + gx0;
      float gf = gsum[4 * tid + 1] + gx1;
      float gg = gsum[4 * tid + 2] + gx2;
      float go = gsum[4 * tid + 3] + gx3;
      c = sigf(gf) * c + sigf(gi) * tanhf(gg);
      float hnew = sigf(go) * tanhf(c);
      g_hench[par ^ 1][start + tid] = __float2half_rn(hnew);
      if (t == SEQ - 1) g_h[start + tid] = hnew;
      __threadfence();
    }
    __syncthreads();
    if (tid == 0) g_arr_enc[b * 32] = (unsigned)(t + 2);
  }
}

// g0[r] = dec_Wih[r] . h_enc + bih[r] + bhh[r]
__global__ void dec_g0_kernel(const float* __restrict__ dwih,
                              const float* __restrict__ bih,
                              const float* __restrict__ bhh) {
  int wid = threadIdx.x >> 5, lane = threadIdx.x & 31;
  int row = blockIdx.x * 8 + wid;
  if (row >= G4I) return;
  const float4* w = (const float4*)(dwih + (size_t)row * EMB);
  const float4* h = (const float4*)g_h;
  float sum = 0.0f;
  for (int k = lane; k < EMB / 4; k += 32) {
    float4 a = w[k], b = h[k];
    sum += a.x * b.x + a.y * b.y + a.z * b.z + a.w * b.w;
  }
#pragma unroll
  for (int o = 16; o; o >>= 1) sum += __shfl_xor_sync(0xffffffffu, sum, o);
  if (lane == 0) g_g0[row] = sum + bih[row] + bhh[row];
}

// Persistent decoder (R8-proven): 57 CTAs, CTA b owns elems [8b, 8b+cnt),
// cnt=8 (9 for b=56); nrows=4*cnt W_eff rows in dynamic SMEM.
__global__ void __launch_bounds__(256, 1) dec_kernel(const float* __restrict__ bih,
                                                     const float* __restrict__ bhh,
                                                     float* __restrict__ out) {
  float* ws   = (float*)esmh;        // 36*INP max
  float* hrs  = ws + 36 * INP;       // INP
  float* bs   = hrs + INP;           // 36
  float* gsum = bs + 36;             // 36
  const int tid = threadIdx.x, wid = tid >> 5, lane = tid & 31, b = blockIdx.x;
  const int cnt = (b == 56) ? 9 : 8;
  const int e0 = 8 * b;
  const int nrows = 4 * cnt;

  for (int idx = tid; idx < nrows * INP; idx += 256) {
    int l = idx / INP, k = idx - l * INP;
    int q = l & 3, el = l >> 2;
    ws[l * INP + k] = g_weff[(size_t)(q * INP + e0 + el) * INP + k];
  }
  if (tid < nrows) {
    int q = tid & 3, el = tid >> 2;
    bs[tid] = bih[q * INP + e0 + el] + bhh[q * INP + e0 + el];
  }
  __syncthreads();

  float c = 0.0f;
  unsigned s = 0;
  for (int t = 0; t < SEQ; t++) {
    if (t > 0) {
      for (int k = tid; k < INP; k += 256) hrs[k] = __ldcg(&g_hraw[(t & 1) * INP + k]);
      __syncthreads();
#pragma unroll 1
      for (int k8 = 0; k8 < 5; k8++) {
        int l = wid + 8 * k8;
        if (l >= nrows) break;  // warp-uniform
        const float* wr = ws + l * INP;
        float sum = 0.0f;
#pragma unroll 5
        for (int k = lane; k < INP; k += 32) sum += wr[k] * hrs[k];
#pragma unroll
        for (int o = 16; o; o >>= 1) sum += __shfl_xor_sync(0xffffffffu, sum, o);
        if (lane == 0) gsum[l] = sum;
      }
      __syncthreads();
    }
    if (tid < cnt) {
      int e = e0 + tid;
      float gi, gf, gg, go;
      if (t == 0) {
        gi = g_g0[e]; gf = g_g0[INP + e]; gg = g_g0[2 * INP + e]; go = g_g0[3 * INP + e];
      } else {
        gi = gsum[4 * tid + 0] + bs[4 * tid + 0];
        gf = gsum[4 * tid + 1] + bs[4 * tid + 1];
        gg = gsum[4 * tid + 2] + bs[4 * tid + 2];
        go = gsum[4 * tid + 3] + bs[4 * tid + 3];
      }
      c = sigf(gf) * c + sigf(gi) * tanhf(gg);
      out[(size_t)(SEQ - 1 - t) * INP + e] = c;
      g_hraw[((t + 1) & 1) * INP + e] = sigf(go) * tanhf(c);
    }
    dbar1(g_arr_dec, ++s, b, tid, DCTA);
  }
}

// In-place row softmax over out[4096][457]
__global__ void softmax_kernel(float* __restrict__ out) {
  __shared__ float red[32];
  const int t = blockIdx.x, tid = threadIdx.x, lane = tid & 31, wid = tid >> 5;
  float v = (tid < INP) ? out[(size_t)t * INP + tid] : -1e30f;
  float m = v;
#pragma unroll
  for (int o = 16; o; o >>= 1) m = fmaxf(m, __shfl_xor_sync(0xffffffffu, m, o));
  if (lane == 0) red[wid] = m;
  __syncthreads();
  m = -1e30f;
  for (int i = 0; i < 16; i++) m = fmaxf(m, red[i]);
  __syncthreads();
  float e = (tid < INP) ? expf(v - m) : 0.0f;
  float sum = e;
#pragma unroll
  for (int o = 16; o; o >>= 1) sum += __shfl_xor_sync(0xffffffffu, sum, o);
  if (lane == 0) red[wid] = sum;
  __syncthreads();
  sum = 0.0f;
  for (int i = 0; i < 16; i++) sum += red[i];
  if (tid < INP) out[(size_t)t * INP + tid] = e / sum;
}

extern "C" void kernel_launch(void* const* d_in, const int* in_sizes, int n_in,
                              void* d_out, int out_size) {
  const float* x    = (const float*)d_in[0];
  const float* eWih = (const float*)d_in[1];
  const float* eWhh = (const float*)d_in[2];
  const float* ebih = (const float*)d_in[3];
  const float* ebhh = (const float*)d_in[4];
  const float* dWih = (const float*)d_in[5];
  const float* dWhh = (const float*)d_in[6];
  const float* dbih = (const float*)d_in[7];
  const float* dbhh = (const float*)d_in[8];
  const float* dWhr = (const float*)d_in[9];
  float* out = (float*)d_out;

  const int enc_smem = (CROWS * EMB + EMB) * 2;                 // 217,088 B
  const int dec_smem = (36 * INP + INP + 72) * 4 + 64;          // ~68 KB
  cudaFuncSetAttribute(enc_kernel, cudaFuncAttributeMaxDynamicSharedMemorySize, enc_smem);
  cudaFuncSetAttribute(dec_kernel, cudaFuncAttributeMaxDynamicSharedMemorySize, dec_smem);

  conv_init_kernel<<<16384, 256>>>(eWhh);
  tr_kernel<<<dim3(256, 15), dim3(32, 8)>>>(eWih);
  gx_kernel<<<dim3(32, 256), 256>>>(x, ebih, ebhh);
  enc_kernel<<<NCTA, 256, enc_smem>>>(eWhh);
  weff_kernel<<<229, 128>>>(dWih, dWhh, dWhr);
  dec_g0_kernel<<<229, 256>>>(dWih, dbih, dbhh);
  dec_kernel<<<DCTA, 256, dec_smem>>>(dbih, dbhh, out);
  softmax_kernel<<<SEQ, 512>>>(out);
}

// round 13
// speedup vs baseline: 3.4098x; 1.3589x over previous
#include <cuda_runtime.h>
#include <cuda_fp16.h>
#include <math.h>
#include <string.h>

#define SEQ 4096
#define INP 457
#define EMB 2048
#define G4E 8192
#define G4I 1828
#define NCTA 148
#define DCTA 57
#define CROWS 52   // fp16 Whh rows cached in SMEM per encoder CTA

__device__ float g_gx[(size_t)SEQ * G4E];     // Wih@x + biases, per timestep
__device__ float g_wihT[(size_t)INP * G4E];   // enc_Wih transposed
__device__ __half g_whh_h[(size_t)G4E * EMB]; // enc_Whh in fp16
__device__ float g_weff[(size_t)G4I * INP];   // (dec_Wih+dec_Whh)@dec_Whr
__device__ float g_g0[G4I];                   // decoder step-0 gates
__device__ float g_h[2 * EMB];                // encoder hidden fp32, double-buffered
__device__ float g_hraw[2 * INP];             // decoder raw hidden, double-buffered
__device__ volatile unsigned g_arr_enc[NCTA * 32];  // one 128B line per CTA
__device__ volatile unsigned g_arr_dec[DCTA * 32];

__device__ __forceinline__ float sigf(float x) { return 1.0f / (1.0f + expf(-x)); }

__device__ __forceinline__ __half2 u2h2(unsigned u) {
  __half2 h; memcpy(&h, &u, 4); return h;
}

// Single-handshake distributed barrier, line-padded flags (R8-proven).
__device__ __forceinline__ void dbar1(volatile unsigned* arr, unsigned s,
                                      int b, int tid, int n) {
  __threadfence();
  __syncthreads();
  if (tid == 0) arr[b * 32] = s;
  if (tid < n) { while (arr[tid * 32] < s) {} }
  __threadfence();
  __syncthreads();
}

// fp16 conversion of enc_Whh + flag/hidden init (fused, launch #0).
__global__ void conv_init_kernel(const float* __restrict__ whh) {
  size_t i = (size_t)blockIdx.x * blockDim.x + threadIdx.x;
  size_t i4 = i * 4;
  float4 v = *(const float4*)(whh + i4);
  __half2* dst = (__half2*)(g_whh_h + i4);
  dst[0] = __floats2half2_rn(v.x, v.y);
  dst[1] = __floats2half2_rn(v.z, v.w);
  if (i < NCTA * 32) g_arr_enc[i] = 0u;
  if (i < DCTA * 32) g_arr_dec[i] = 0u;
  if (i < EMB) g_h[i] = 0.0f;  // encoder reads buffer 0 at t=0
}

// Transpose enc_Wih [8192][457] -> g_wihT [457][8192]
__global__ void tr_kernel(const float* __restrict__ in) {
  __shared__ float tile[32][33];
  int r0 = blockIdx.x * 32, c0 = blockIdx.y * 32;
  int x = threadIdx.x;
  for (int y = threadIdx.y; y < 32; y += 8) {
    int c = c0 + x;
    if (c < INP) tile[y][x] = in[(size_t)(r0 + y) * INP + c];
  }
  __syncthreads();
  for (int y = threadIdx.y; y < 32; y += 8) {
    int c = c0 + y;
    if (c < INP) g_wihT[(size_t)c * G4E + r0 + x] = tile[x][y];
  }
}

// Gx[t][r] = sum_k x[t][k]*Wih[r][k] + bih[r] + bhh[r]
__global__ void __launch_bounds__(256) gx_kernel(const float* __restrict__ x,
                                                 const float* __restrict__ bih,
                                                 const float* __restrict__ bhh) {
  __shared__ float xs[INP * 20];
  const int tid = threadIdx.x;
  const int rb = blockIdx.x * 256, tb = blockIdx.y * 16;
  for (int i = tid; i < 16 * INP; i += 256) {
    int tt = i / INP, k = i - tt * INP;
    xs[k * 20 + tt] = x[(size_t)(tb + tt) * INP + k];
  }
  __syncthreads();
  const int r = rb + tid;
  float acc[16];
#pragma unroll
  for (int j = 0; j < 16; j++) acc[j] = 0.0f;
  for (int k = 0; k < INP; k++) {
    float w = g_wihT[(size_t)k * G4E + r];
    const float4* xv = (const float4*)(xs + k * 20);
    float4 a = xv[0], b = xv[1], c = xv[2], d = xv[3];
    acc[0]  += w * a.x; acc[1]  += w * a.y; acc[2]  += w * a.z; acc[3]  += w * a.w;
    acc[4]  += w * b.x; acc[5]  += w * b.y; acc[6]  += w * b.z; acc[7]  += w * b.w;
    acc[8]  += w * c.x; acc[9]  += w * c.y; acc[10] += w * c.z; acc[11] += w * c.w;
    acc[12] += w * d.x; acc[13] += w * d.y; acc[14] += w * d.z; acc[15] += w * d.w;
  }
  float bsum = bih[r] + bhh[r];
#pragma unroll
  for (int j = 0; j < 16; j++) g_gx[(size_t)(tb + j) * G4E + r] = acc[j] + bsum;
}

// W_eff[r][j] = sum_m (dWih[r][m]+dWhh[r][m]) * dWhr[m][j]
__global__ void __launch_bounds__(128) weff_kernel(const float* __restrict__ dwih,
                                                   const float* __restrict__ dwhh,
                                                   const float* __restrict__ whr) {
  __shared__ float wcs[8 * 128];
  const int tid = threadIdx.x;
  const int r0 = blockIdx.x * 8;
  float acc[8][4];
#pragma unroll
  for (int i = 0; i < 8; i++)
#pragma unroll
    for (int j = 0; j < 4; j++) acc[i][j] = 0.0f;

  for (int kb = 0; kb < EMB; kb += 128) {
    __syncthreads();
#pragma unroll
    for (int i = 0; i < 8; i++) {
      int row = r0 + i; if (row > G4I - 1) row = G4I - 1;
      size_t idx = (size_t)row * EMB + kb + tid;
      wcs[i * 128 + tid] = dwih[idx] + dwhh[idx];
    }
    __syncthreads();
#pragma unroll 4
    for (int kk = 0; kk < 128; kk++) {
      const float* wrow = whr + (size_t)(kb + kk) * INP;
      float v0 = wrow[tid];
      float v1 = wrow[tid + 128];
      float v2 = wrow[tid + 256];
      float v3 = (tid < 73) ? wrow[tid + 384] : 0.0f;
#pragma unroll
      for (int i = 0; i < 8; i++) {
        float w = wcs[i * 128 + kk];
        acc[i][0] += w * v0; acc[i][1] += w * v1;
        acc[i][2] += w * v2; acc[i][3] += w * v3;
      }
    }
  }
#pragma unroll
  for (int i = 0; i < 8; i++) {
    int row = r0 + i;
    if (row < G4I) {
      size_t rb = (size_t)row * INP;
      g_weff[rb + tid]       = acc[i][0];
      g_weff[rb + tid + 128] = acc[i][1];
      g_weff[rb + tid + 256] = acc[i][2];
      if (tid < 73) g_weff[rb + tid + 384] = acc[i][3];
    }
  }
}

// Persistent encoder: fp16 weights, HFMA2 inner loop with 4 independent
// half2 accumulators, fp32 h exchange (R8 scheme), next-step Gx prefetch.
// CTA b owns cnt (14/13) hidden elems at start; gate rows i = 4*el + q.
extern __shared__ __half esmh[];
__global__ void __launch_bounds__(256, 1) enc_kernel() {
  __shared__ float gsum[64];
  const int tid = threadIdx.x, wid = tid >> 5, lane = tid & 31, b = blockIdx.x;
  const int cnt   = (b < 124) ? 14 : 13;
  const int start = (b < 124) ? 14 * b : 1736 + 13 * (b - 124);
  const int nrows = 4 * cnt;
  __half* ws  = esmh;                       // CROWS * 2048 halfs
  __half* hs2 = esmh + (size_t)CROWS * EMB; // 2048 halfs (h staging)

  for (int idx = tid; idx < CROWS * EMB; idx += 256) {
    int i = idx >> 11, k = idx & 2047;
    int e = start + (i >> 2), q = i & 3;
    ws[idx] = g_whh_h[((size_t)(q << 11) + e) * EMB + k];
  }
  __syncthreads();

  float c = 0.0f;
  unsigned s = 0;
  // Prefetch Gx for t=0.
  float gx0 = 0.f, gx1 = 0.f, gx2 = 0.f, gx3 = 0.f;
  if (tid < cnt) {
    size_t base = start + tid;
    gx0 = __ldcg(&g_gx[base]);
    gx1 = __ldcg(&g_gx[base + 2048]);
    gx2 = __ldcg(&g_gx[base + 4096]);
    gx3 = __ldcg(&g_gx[base + 6144]);
  }

  for (int t = 0; t < SEQ; t++) {
    // Stage h (fp32 global, coalesced) into SMEM as half2.
    const float4* h4g = (const float4*)(g_h + (t & 1) * EMB);
    for (int i = tid; i < EMB / 4; i += 256) {
      float4 v = __ldcg(h4g + i);
      __half2* d = (__half2*)(hs2 + i * 4);
      d[0] = __floats2half2_rn(v.x, v.y);
      d[1] = __floats2half2_rn(v.z, v.w);
    }
    __syncthreads();

    // Lane-partition of h: slot j holds halfs [8*(lane+32j), +8).
    uint4 hreg[8];
    const uint4* h4 = (const uint4*)hs2;
#pragma unroll
    for (int j = 0; j < 8; j++) hreg[j] = h4[lane + 32 * j];

#pragma unroll 1
    for (int k = 0; k < 7; k++) {
      int i = wid + 8 * k;
      if (i >= nrows) break;  // warp-uniform
      __half2 a0 = __floats2half2_rn(0.f, 0.f), a1 = a0, a2 = a0, a3 = a0;
      if (i < CROWS) {
        const uint4* wr = (const uint4*)(ws + (size_t)i * EMB);
#pragma unroll
        for (int j = 0; j < 8; j++) {
          uint4 w = wr[lane + 32 * j];
          a0 = __hfma2(u2h2(w.x), u2h2(hreg[j].x), a0);
          a1 = __hfma2(u2h2(w.y), u2h2(hreg[j].y), a1);
          a2 = __hfma2(u2h2(w.z), u2h2(hreg[j].z), a2);
          a3 = __hfma2(u2h2(w.w), u2h2(hreg[j].w), a3);
        }
      } else {
        int e = start + (i >> 2), q = i & 3;
        const uint4* wr = (const uint4*)(g_whh_h + ((size_t)(q << 11) + e) * EMB);
#pragma unroll
        for (int j = 0; j < 8; j++) {
          uint4 w = __ldcg(wr + lane + 32 * j);
          a0 = __hfma2(u2h2(w.x), u2h2(hreg[j].x), a0);
          a1 = __hfma2(u2h2(w.y), u2h2(hreg[j].y), a1);
          a2 = __hfma2(u2h2(w.z), u2h2(hreg[j].z), a2);
          a3 = __hfma2(u2h2(w.w), u2h2(hreg[j].w), a3);
        }
      }
      float2 f0 = __half22float2(a0), f1 = __half22float2(a1);
      float2 f2 = __half22float2(a2), f3 = __half22float2(a3);
      float sum = (f0.x + f0.y) + (f1.x + f1.y) + (f2.x + f2.y) + (f3.x + f3.y);
#pragma unroll
      for (int o = 16; o; o >>= 1) sum += __shfl_xor_sync(0xffffffffu, sum, o);
      if (lane == 0) gsum[i] = sum;
    }
    __syncthreads();

    if (tid < cnt) {
      float gi = gsum[4 * tid + 0] + gx0;
      float gf = gsum[4 * tid + 1] + gx1;
      float gg = gsum[4 * tid + 2] + gx2;
      float go = gsum[4 * tid + 3] + gx3;
      c = sigf(gf) * c + sigf(gi) * tanhf(gg);
      g_h[((t + 1) & 1) * EMB + start + tid] = sigf(go) * tanhf(c);
      // Prefetch next step's Gx before the barrier (hides L2 latency).
      if (t + 1 < SEQ) {
        size_t base = (size_t)(t + 1) * G4E + start + tid;
        gx0 = __ldcg(&g_gx[base]);
        gx1 = __ldcg(&g_gx[base + 2048]);
        gx2 = __ldcg(&g_gx[base + 4096]);
        gx3 = __ldcg(&g_gx[base + 6144]);
      }
    }
    dbar1(g_arr_enc, ++s, b, tid, NCTA);
  }
}

// g0[r] = dec_Wih[r] . h_enc + bih[r] + bhh[r]  (h_enc = g_h buffer 0; SEQ even)
__global__ void dec_g0_kernel(const float* __restrict__ dwih,
                              const float* __restrict__ bih,
                              const float* __restrict__ bhh) {
  int wid = threadIdx.x >> 5, lane = threadIdx.x & 31;
  int row = blockIdx.x * 8 + wid;
  if (row >= G4I) return;
  const float4* w = (const float4*)(dwih + (size_t)row * EMB);
  const float4* h = (const float4*)g_h;
  float sum = 0.0f;
  for (int k = lane; k < EMB / 4; k += 32) {
    float4 a = w[k], b = h[k];
    sum += a.x * b.x + a.y * b.y + a.z * b.z + a.w * b.w;
  }
#pragma unroll
  for (int o = 16; o; o >>= 1) sum += __shfl_xor_sync(0xffffffffu, sum, o);
  if (lane == 0) g_g0[row] = sum + bih[row] + bhh[row];
}

// Persistent decoder (R8-proven): 57 CTAs, CTA b owns elems [8b, 8b+cnt),
// cnt=8 (9 for b=56); nrows=4*cnt W_eff rows in dynamic SMEM.
__global__ void __launch_bounds__(256, 1) dec_kernel(const float* __restrict__ bih,
                                                     const float* __restrict__ bhh,
                                                     float* __restrict__ out) {
  float* ws   = (float*)esmh;        // 36*INP max
  float* hrs  = ws + 36 * INP;       // INP
  float* bs   = hrs + INP;           // 36
  float* gsum = bs + 36;             // 36
  const int tid = threadIdx.x, wid = tid >> 5, lane = tid & 31, b = blockIdx.x;
  const int cnt = (b == 56) ? 9 : 8;
  const int e0 = 8 * b;
  const int nrows = 4 * cnt;

  for (int idx = tid; idx < nrows * INP; idx += 256) {
    int l = idx / INP, k = idx - l * INP;
    int q = l & 3, el = l >> 2;
    ws[l * INP + k] = g_weff[(size_t)(q * INP + e0 + el) * INP + k];
  }
  if (tid < nrows) {
    int q = tid & 3, el = tid >> 2;
    bs[tid] = bih[q * INP + e0 + el] + bhh[q * INP + e0 + el];
  }
  __syncthreads();

  float c = 0.0f;
  unsigned s = 0;
  for (int t = 0; t < SEQ; t++) {
    if (t > 0) {
      for (int k = tid; k < INP; k += 256) hrs[k] = __ldcg(&g_hraw[(t & 1) * INP + k]);
      __syncthreads();
#pragma unroll 1
      for (int k8 = 0; k8 < 5; k8++) {
        int l = wid + 8 * k8;
        if (l >= nrows) break;  // warp-uniform
        const float* wr = ws + l * INP;
        float sum = 0.0f;
#pragma unroll 5
        for (int k = lane; k < INP; k += 32) sum += wr[k] * hrs[k];
#pragma unroll
        for (int o = 16; o; o >>= 1) sum += __shfl_xor_sync(0xffffffffu, sum, o);
        if (lane == 0) gsum[l] = sum;
      }
      __syncthreads();
    }
    if (tid < cnt) {
      int e = e0 + tid;
      float gi, gf, gg, go;
      if (t == 0) {
        gi = g_g0[e]; gf = g_g0[INP + e]; gg = g_g0[2 * INP + e]; go = g_g0[3 * INP + e];
      } else {
        gi = gsum[4 * tid + 0] + bs[4 * tid + 0];
        gf = gsum[4 * tid + 1] + bs[4 * tid + 1];
        gg = gsum[4 * tid + 2] + bs[4 * tid + 2];
        go = gsum[4 * tid + 3] + bs[4 * tid + 3];
      }
      c = sigf(gf) * c + sigf(gi) * tanhf(gg);
      out[(size_t)(SEQ - 1 - t) * INP + e] = c;
      g_hraw[((t + 1) & 1) * INP + e] = sigf(go) * tanhf(c);
    }
    dbar1(g_arr_dec, ++s, b, tid, DCTA);
  }
}

// In-place row softmax over out[4096][457]
__global__ void softmax_kernel(float* __restrict__ out) {
  __shared__ float red[32];
  const int t = blockIdx.x, tid = threadIdx.x, lane = tid & 31, wid = tid >> 5;
  float v = (tid < INP) ? out[(size_t)t * INP + tid] : -1e30f;
  float m = v;
#pragma unroll
  for (int o = 16; o; o >>= 1) m = fmaxf(m, __shfl_xor_sync(0xffffffffu, m, o));
  if (lane == 0) red[wid] = m;
  __syncthreads();
  m = -1e30f;
  for (int i = 0; i < 16; i++) m = fmaxf(m, red[i]);
  __syncthreads();
  float e = (tid < INP) ? expf(v - m) : 0.0f;
  float sum = e;
#pragma unroll
  for (int o = 16; o; o >>= 1) sum += __shfl_xor_sync(0xffffffffu, sum, o);
  if (lane == 0) red[wid] = sum;
  __syncthreads();
  sum = 0.0f;
  for (int i = 0; i < 16; i++) sum += red[i];
  if (tid < INP) out[(size_t)t * INP + tid] = e / sum;
}

extern "C" void kernel_launch(void* const* d_in, const int* in_sizes, int n_in,
                              void* d_out, int out_size) {
  const float* x    = (const float*)d_in[0];
  const float* eWih = (const float*)d_in[1];
  const float* eWhh = (const float*)d_in[2];
  const float* ebih = (const float*)d_in[3];
  const float* ebhh = (const float*)d_in[4];
  const float* dWih = (const float*)d_in[5];
  const float* dWhh = (const float*)d_in[6];
  const float* dbih = (const float*)d_in[7];
  const float* dbhh = (const float*)d_in[8];
  const float* dWhr = (const float*)d_in[9];
  float* out = (float*)d_out;

  const int enc_smem = (CROWS * EMB + EMB) * 2;                 // 217,088 B
  const int dec_smem = (36 * INP + INP + 72) * 4 + 64;          // ~68 KB
  cudaFuncSetAttribute(enc_kernel, cudaFuncAttributeMaxDynamicSharedMemorySize, enc_smem);
  cudaFuncSetAttribute(dec_kernel, cudaFuncAttributeMaxDynamicSharedMemorySize, dec_smem);

  conv_init_kernel<<<16384, 256>>>(eWhh);
  tr_kernel<<<dim3(256, 15), dim3(32, 8)>>>(eWih);
  gx_kernel<<<dim3(32, 256), 256>>>(x, ebih, ebhh);
  enc_kernel<<<NCTA, 256, enc_smem>>>();
  weff_kernel<<<229, 128>>>(dWih, dWhh, dWhr);
  dec_g0_kernel<<<229, 256>>>(dWih, dbih, dbhh);
  dec_kernel<<<DCTA, 256, dec_smem>>>(dbih, dbhh, out);
  softmax_kernel<<<SEQ, 512>>>(out);
}

// round 14
// speedup vs baseline: 4.4731x; 1.3118x over previous
#include <cuda_runtime.h>
#include <cuda_fp16.h>
#include <math.h>
#include <string.h>

#define SEQ 4096
#define INP 457
#define EMB 2048
#define G4E 8192
#define G4I 1828
#define NCTA 148
#define DCTA 57
#define CROWS 52   // fp16 Whh rows cached in SMEM per encoder CTA (rows 52-55 in regs)

__device__ float g_gx[(size_t)SEQ * G4E];     // Wih@x + biases, per timestep
__device__ float g_wihT[(size_t)INP * G4E];   // enc_Wih transposed
__device__ __half g_whh_h[(size_t)G4E * EMB]; // enc_Whh in fp16
__device__ float g_weff[(size_t)G4I * INP];   // (dec_Wih+dec_Whh)@dec_Whr
__device__ float g_g0[G4I];                   // decoder step-0 gates
__device__ float g_h[EMB];                    // final encoder hidden fp32 (for dec_g0)
__device__ uint4 g_hhu[2][256];               // encoder hidden fp16, double-buffered (4KB each)
__device__ float g_hraw[2 * INP];             // decoder raw hidden fp32, double-buffered
// Packed flags: 4 flags (4B each) in the first 16B of each 128B line.
__device__ uint4 g_flag_enc4[37 * 8];         // 148 flags -> 37 groups
__device__ uint4 g_flag_dec4[15 * 8];         // 57 flags  -> 15 groups (3 pad slots)

__device__ __forceinline__ float sigf(float x) { return 1.0f / (1.0f + expf(-x)); }

__device__ __forceinline__ __half2 u2h2(unsigned u) {
  __half2 h; memcpy(&h, &u, 4); return h;
}

// Poll one packed group of 4 flags until all >= tgt.
__device__ __forceinline__ void poll4(const uint4* gp, unsigned tgt) {
  unsigned v0, v1, v2, v3;
  do {
    asm volatile("ld.global.cg.v4.u32 {%0,%1,%2,%3},[%4];"
                 : "=r"(v0), "=r"(v1), "=r"(v2), "=r"(v3) : "l"(gp) : "memory");
  } while (v0 < tgt || v1 < tgt || v2 < tgt || v3 < tgt);
}

// fp16 conversion of enc_Whh + flag/hidden init (fused, launch #0).
__global__ void conv_init_kernel(const float* __restrict__ whh) {
  size_t i = (size_t)blockIdx.x * blockDim.x + threadIdx.x;
  size_t i4 = i * 4;
  float4 v = *(const float4*)(whh + i4);
  __half2* dst = (__half2*)(g_whh_h + i4);
  dst[0] = __floats2half2_rn(v.x, v.y);
  dst[1] = __floats2half2_rn(v.z, v.w);
  unsigned* fe = (unsigned*)g_flag_enc4;
  unsigned* fd = (unsigned*)g_flag_dec4;
  if (i < 37u * 32u) fe[i] = 0u;
  if (i < 15u * 32u) {
    // group 14 words 1..3 are padding: make them always-passing
    fd[i] = (i > 14u * 32u && i < 14u * 32u + 4u) ? 0x7FFFFFFFu : 0u;
  }
  if (i < 512u) ((uint4*)g_hhu)[i] = make_uint4(0u, 0u, 0u, 0u);  // h_0 = 0
}

// Transpose enc_Wih [8192][457] -> g_wihT [457][8192]
__global__ void tr_kernel(const float* __restrict__ in) {
  __shared__ float tile[32][33];
  int r0 = blockIdx.x * 32, c0 = blockIdx.y * 32;
  int x = threadIdx.x;
  for (int y = threadIdx.y; y < 32; y += 8) {
    int c = c0 + x;
    if (c < INP) tile[y][x] = in[(size_t)(r0 + y) * INP + c];
  }
  __syncthreads();
  for (int y = threadIdx.y; y < 32; y += 8) {
    int c = c0 + y;
    if (c < INP) g_wihT[(size_t)c * G4E + r0 + x] = tile[x][y];
  }
}

// Gx[t][r] = sum_k x[t][k]*Wih[r][k] + bih[r] + bhh[r]
__global__ void __launch_bounds__(256) gx_kernel(const float* __restrict__ x,
                                                 const float* __restrict__ bih,
                                                 const float* __restrict__ bhh) {
  __shared__ float xs[INP * 20];
  const int tid = threadIdx.x;
  const int rb = blockIdx.x * 256, tb = blockIdx.y * 16;
  for (int i = tid; i < 16 * INP; i += 256) {
    int tt = i / INP, k = i - tt * INP;
    xs[k * 20 + tt] = x[(size_t)(tb + tt) * INP + k];
  }
  __syncthreads();
  const int r = rb + tid;
  float acc[16];
#pragma unroll
  for (int j = 0; j < 16; j++) acc[j] = 0.0f;
  for (int k = 0; k < INP; k++) {
    float w = g_wihT[(size_t)k * G4E + r];
    const float4* xv = (const float4*)(xs + k * 20);
    float4 a = xv[0], b = xv[1], c = xv[2], d = xv[3];
    acc[0]  += w * a.x; acc[1]  += w * a.y; acc[2]  += w * a.z; acc[3]  += w * a.w;
    acc[4]  += w * b.x; acc[5]  += w * b.y; acc[6]  += w * b.z; acc[7]  += w * b.w;
    acc[8]  += w * c.x; acc[9]  += w * c.y; acc[10] += w * c.z; acc[11] += w * c.w;
    acc[12] += w * d.x; acc[13] += w * d.y; acc[14] += w * d.z; acc[15] += w * d.w;
  }
  float bsum = bih[r] + bhh[r];
#pragma unroll
  for (int j = 0; j < 16; j++) g_gx[(size_t)(tb + j) * G4E + r] = acc[j] + bsum;
}

// W_eff[r][j] = sum_m (dWih[r][m]+dWhh[r][m]) * dWhr[m][j]
__global__ void __launch_bounds__(128) weff_kernel(const float* __restrict__ dwih,
                                                   const float* __restrict__ dwhh,
                                                   const float* __restrict__ whr) {
  __shared__ float wcs[8 * 128];
  const int tid = threadIdx.x;
  const int r0 = blockIdx.x * 8;
  float acc[8][4];
#pragma unroll
  for (int i = 0; i < 8; i++)
#pragma unroll
    for (int j = 0; j < 4; j++) acc[i][j] = 0.0f;

  for (int kb = 0; kb < EMB; kb += 128) {
    __syncthreads();
#pragma unroll
    for (int i = 0; i < 8; i++) {
      int row = r0 + i; if (row > G4I - 1) row = G4I - 1;
      size_t idx = (size_t)row * EMB + kb + tid;
      wcs[i * 128 + tid] = dwih[idx] + dwhh[idx];
    }
    __syncthreads();
#pragma unroll 4
    for (int kk = 0; kk < 128; kk++) {
      const float* wrow = whr + (size_t)(kb + kk) * INP;
      float v0 = wrow[tid];
      float v1 = wrow[tid + 128];
      float v2 = wrow[tid + 256];
      float v3 = (tid < 73) ? wrow[tid + 384] : 0.0f;
#pragma unroll
      for (int i = 0; i < 8; i++) {
        float w = wcs[i * 128 + kk];
        acc[i][0] += w * v0; acc[i][1] += w * v1;
        acc[i][2] += w * v2; acc[i][3] += w * v3;
      }
    }
  }
#pragma unroll
  for (int i = 0; i < 8; i++) {
    int row = r0 + i;
    if (row < G4I) {
      size_t rb = (size_t)row * INP;
      g_weff[rb + tid]       = acc[i][0];
      g_weff[rb + tid + 128] = acc[i][1];
      g_weff[rb + tid + 256] = acc[i][2];
      if (tid < 73) g_weff[rb + tid + 384] = acc[i][3];
    }
  }
}

// Persistent encoder: fp16 weights (52 rows SMEM + 4 rows in registers),
// HFMA2 with 4 independent accumulators, fp16 h exchange (one uint4/thread),
// packed-flag barrier, warp0 publish, early Gx prefetch.
extern __shared__ __half esmh[];
__global__ void __launch_bounds__(256, 1) enc_kernel() {
  __shared__ float gsum[64];
  const int tid = threadIdx.x, wid = tid >> 5, lane = tid & 31, b = blockIdx.x;
  const int cnt   = (b < 124) ? 14 : 13;
  const int start = (b < 124) ? 14 * b : 1736 + 13 * (b - 124);
  const int nrows = 4 * cnt;
  __half* ws  = esmh;                       // CROWS * 2048 halfs
  __half* hs2 = esmh + (size_t)CROWS * EMB; // 2048 halfs (h staging)

  for (int idx = tid; idx < CROWS * EMB; idx += 256) {
    int i = idx >> 11, k = idx & 2047;
    int e = start + (i >> 2), q = i & 3;
    ws[idx] = g_whh_h[((size_t)(q << 11) + e) * EMB + k];
  }
  // Register-resident rows 52..55 (warps 4..7, row = 48+wid), if in range.
  uint4 wreg[8];
  const int regrow = 48 + wid;
  const bool hasreg = (wid >= 4) && (regrow < nrows);
  if (hasreg) {
    int e = start + (regrow >> 2), q = regrow & 3;
    const uint4* wr = (const uint4*)(g_whh_h + ((size_t)(q << 11) + e) * EMB);
#pragma unroll
    for (int j = 0; j < 8; j++) wreg[j] = __ldcg(wr + lane + 32 * j);
  }
  __syncthreads();

  float c = 0.0f;
  float gx0 = 0.f, gx1 = 0.f, gx2 = 0.f, gx3 = 0.f;
  if (tid < cnt) {
    size_t base = start + tid;
    gx0 = __ldcg(&g_gx[base]);
    gx1 = __ldcg(&g_gx[base + 2048]);
    gx2 = __ldcg(&g_gx[base + 4096]);
    gx3 = __ldcg(&g_gx[base + 6144]);
  }

  for (int t = 0; t < SEQ; t++) {
    // Stage h (fp16, 4KB): exactly one uint4 per thread.
    ((uint4*)hs2)[tid] = __ldcg(&((const uint4*)g_hhu)[(t & 1) * 256 + tid]);
    __syncthreads();

    // Early prefetch of next step's Gx (lands during the dot product).
    float pf0 = 0.f, pf1 = 0.f, pf2 = 0.f, pf3 = 0.f;
    if (tid < cnt && t + 1 < SEQ) {
      size_t base = (size_t)(t + 1) * G4E + start + tid;
      pf0 = __ldcg(&g_gx[base]);
      pf1 = __ldcg(&g_gx[base + 2048]);
      pf2 = __ldcg(&g_gx[base + 4096]);
      pf3 = __ldcg(&g_gx[base + 6144]);
    }

    uint4 hreg[8];
    const uint4* h4 = (const uint4*)hs2;
#pragma unroll
    for (int j = 0; j < 8; j++) hreg[j] = h4[lane + 32 * j];

#pragma unroll 1
    for (int k = 0; k < 6; k++) {      // rows 0..47: all SMEM
      int i = wid + 8 * k;
      const uint4* wr = (const uint4*)(ws + (size_t)i * EMB);
      __half2 a0 = __floats2half2_rn(0.f, 0.f), a1 = a0, a2 = a0, a3 = a0;
#pragma unroll
      for (int j = 0; j < 8; j++) {
        uint4 w = wr[lane + 32 * j];
        a0 = __hfma2(u2h2(w.x), u2h2(hreg[j].x), a0);
        a1 = __hfma2(u2h2(w.y), u2h2(hreg[j].y), a1);
        a2 = __hfma2(u2h2(w.z), u2h2(hreg[j].z), a2);
        a3 = __hfma2(u2h2(w.w), u2h2(hreg[j].w), a3);
      }
      float2 f0 = __half22float2(a0), f1 = __half22float2(a1);
      float2 f2 = __half22float2(a2), f3 = __half22float2(a3);
      float sum = (f0.x + f0.y) + (f1.x + f1.y) + (f2.x + f2.y) + (f3.x + f3.y);
#pragma unroll
      for (int o = 16; o; o >>= 1) sum += __shfl_xor_sync(0xffffffffu, sum, o);
      if (lane == 0) gsum[i] = sum;
    }
    {  // rows 48..55: SMEM for wid<4, registers for wid>=4
      int i = 48 + wid;
      if (i < nrows) {
        __half2 a0 = __floats2half2_rn(0.f, 0.f), a1 = a0, a2 = a0, a3 = a0;
        if (wid < 4) {
          const uint4* wr = (const uint4*)(ws + (size_t)i * EMB);
#pragma unroll
          for (int j = 0; j < 8; j++) {
            uint4 w = wr[lane + 32 * j];
            a0 = __hfma2(u2h2(w.x), u2h2(hreg[j].x), a0);
            a1 = __hfma2(u2h2(w.y), u2h2(hreg[j].y), a1);
            a2 = __hfma2(u2h2(w.z), u2h2(hreg[j].z), a2);
            a3 = __hfma2(u2h2(w.w), u2h2(hreg[j].w), a3);
          }
        } else {
#pragma unroll
          for (int j = 0; j < 8; j++) {
            uint4 w = wreg[j];
            a0 = __hfma2(u2h2(w.x), u2h2(hreg[j].x), a0);
            a1 = __hfma2(u2h2(w.y), u2h2(hreg[j].y), a1);
            a2 = __hfma2(u2h2(w.z), u2h2(hreg[j].z), a2);
            a3 = __hfma2(u2h2(w.w), u2h2(hreg[j].w), a3);
          }
        }
        float2 f0 = __half22float2(a0), f1 = __half22float2(a1);
        float2 f2 = __half22float2(a2), f3 = __half22float2(a3);
        float sum = (f0.x + f0.y) + (f1.x + f1.y) + (f2.x + f2.y) + (f3.x + f3.y);
#pragma unroll
        for (int o = 16; o; o >>= 1) sum += __shfl_xor_sync(0xffffffffu, sum, o);
        if (lane == 0) gsum[i] = sum;
      }
    }
    __syncthreads();

    if (tid < cnt) {
      float gi = gsum[4 * tid + 0] + gx0;
      float gf = gsum[4 * tid + 1] + gx1;
      float gg = gsum[4 * tid + 2] + gx2;
      float go = gsum[4 * tid + 3] + gx3;
      c = sigf(gf) * c + sigf(gi) * tanhf(gg);
      float hnew = sigf(go) * tanhf(c);
      ((__half*)g_hhu)[((t + 1) & 1) * 2048 + start + tid] = __float2half_rn(hnew);
      if (t == SEQ - 1) g_h[start + tid] = hnew;
      __threadfence();
    }
    gx0 = pf0; gx1 = pf1; gx2 = pf2; gx3 = pf3;

    if (t + 1 < SEQ) {
      __syncwarp();  // warp0: order writers' fences before flag store
      if (tid == 0)
        ((volatile unsigned*)g_flag_enc4)[(b >> 2) * 32 + (b & 3)] = (unsigned)(t + 1);
      if (tid < 37) {
        poll4(g_flag_enc4 + tid * 8, (unsigned)(t + 1));
        __threadfence();
      }
      __syncthreads();
    }
  }
}

// g0[r] = dec_Wih[r] . h_enc + bih[r] + bhh[r]
__global__ void dec_g0_kernel(const float* __restrict__ dwih,
                              const float* __restrict__ bih,
                              const float* __restrict__ bhh) {
  int wid = threadIdx.x >> 5, lane = threadIdx.x & 31;
  int row = blockIdx.x * 8 + wid;
  if (row >= G4I) return;
  const float4* w = (const float4*)(dwih + (size_t)row * EMB);
  const float4* h = (const float4*)g_h;
  float sum = 0.0f;
  for (int k = lane; k < EMB / 4; k += 32) {
    float4 a = w[k], b = h[k];
    sum += a.x * b.x + a.y * b.y + a.z * b.z + a.w * b.w;
  }
#pragma unroll
  for (int o = 16; o; o >>= 1) sum += __shfl_xor_sync(0xffffffffu, sum, o);
  if (lane == 0) g_g0[row] = sum + bih[row] + bhh[row];
}

// Persistent decoder: 57 CTAs (fp32 throughout), packed-flag barrier, warp0 publish.
__global__ void __launch_bounds__(256, 1) dec_kernel(const float* __restrict__ bih,
                                                     const float* __restrict__ bhh,
                                                     float* __restrict__ out) {
  float* ws   = (float*)esmh;        // 36*INP max
  float* hrs  = ws + 36 * INP;       // INP
  float* bs   = hrs + INP;           // 36
  float* gsum = bs + 36;             // 36
  const int tid = threadIdx.x, wid = tid >> 5, lane = tid & 31, b = blockIdx.x;
  const int cnt = (b == 56) ? 9 : 8;
  const int e0 = 8 * b;
  const int nrows = 4 * cnt;

  for (int idx = tid; idx < nrows * INP; idx += 256) {
    int l = idx / INP, k = idx - l * INP;
    int q = l & 3, el = l >> 2;
    ws[l * INP + k] = g_weff[(size_t)(q * INP + e0 + el) * INP + k];
  }
  if (tid < nrows) {
    int q = tid & 3, el = tid >> 2;
    bs[tid] = bih[q * INP + e0 + el] + bhh[q * INP + e0 + el];
  }
  __syncthreads();

  float c = 0.0f;
  for (int t = 0; t < SEQ; t++) {
    if (t > 0) {
      for (int k = tid; k < INP; k += 256) hrs[k] = __ldcg(&g_hraw[(t & 1) * INP + k]);
      __syncthreads();
#pragma unroll 1
      for (int k8 = 0; k8 < 5; k8++) {
        int l = wid + 8 * k8;
        if (l >= nrows) break;  // warp-uniform
        const float* wr = ws + l * INP;
        float sum = 0.0f;
#pragma unroll 5
        for (int k = lane; k < INP; k += 32) sum += wr[k] * hrs[k];
#pragma unroll
        for (int o = 16; o; o >>= 1) sum += __shfl_xor_sync(0xffffffffu, sum, o);
        if (lane == 0) gsum[l] = sum;
      }
      __syncthreads();
    }
    if (tid < cnt) {
      int e = e0 + tid;
      float gi, gf, gg, go;
      if (t == 0) {
        gi = g_g0[e]; gf = g_g0[INP + e]; gg = g_g0[2 * INP + e]; go = g_g0[3 * INP + e];
      } else {
        gi = gsum[4 * tid + 0] + bs[4 * tid + 0];
        gf = gsum[4 * tid + 1] + bs[4 * tid + 1];
        gg = gsum[4 * tid + 2] + bs[4 * tid + 2];
        go = gsum[4 * tid + 3] + bs[4 * tid + 3];
      }
      c = sigf(gf) * c + sigf(gi) * tanhf(gg);
      out[(size_t)(SEQ - 1 - t) * INP + e] = c;
      g_hraw[((t + 1) & 1) * INP + e] = sigf(go) * tanhf(c);
      __threadfence();
    }
    if (t + 1 < SEQ) {
      __syncwarp();
      if (tid == 0)
        ((volatile unsigned*)g_flag_dec4)[(b >> 2) * 32 + (b & 3)] = (unsigned)(t + 1);
      if (tid < 15) {
        poll4(g_flag_dec4 + tid * 8, (unsigned)(t + 1));
        __threadfence();
      }
      __syncthreads();
    }
  }
}

// In-place row softmax over out[4096][457]
__global__ void softmax_kernel(float* __restrict__ out) {
  __shared__ float red[32];
  const int t = blockIdx.x, tid = threadIdx.x, lane = tid & 31, wid = tid >> 5;
  float v = (tid < INP) ? out[(size_t)t * INP + tid] : -1e30f;
  float m = v;
#pragma unroll
  for (int o = 16; o; o >>= 1) m = fmaxf(m, __shfl_xor_sync(0xffffffffu, m, o));
  if (lane == 0) red[wid] = m;
  __syncthreads();
  m = -1e30f;
  for (int i = 0; i < 16; i++) m = fmaxf(m, red[i]);
  __syncthreads();
  float e = (tid < INP) ? expf(v - m) : 0.0f;
  float sum = e;
#pragma unroll
  for (int o = 16; o; o >>= 1) sum += __shfl_xor_sync(0xffffffffu, sum, o);
  if (lane == 0) red[wid] = sum;
  __syncthreads();
  sum = 0.0f;
  for (int i = 0; i < 16; i++) sum += red[i];
  if (tid < INP) out[(size_t)t * INP + tid] = e / sum;
}

extern "C" void kernel_launch(void* const* d_in, const int* in_sizes, int n_in,
                              void* d_out, int out_size) {
  const float* x    = (const float*)d_in[0];
  const float* eWih = (const float*)d_in[1];
  const float* eWhh = (const float*)d_in[2];
  const float* ebih = (const float*)d_in[3];
  const float* ebhh = (const float*)d_in[4];
  const float* dWih = (const float*)d_in[5];
  const float* dWhh = (const float*)d_in[6];
  const float* dbih = (const float*)d_in[7];
  const float* dbhh = (const float*)d_in[8];
  const float* dWhr = (const float*)d_in[9];
  float* out = (float*)d_out;

  const int enc_smem = (CROWS * EMB + EMB) * 2;                 // 217,088 B
  const int dec_smem = (36 * INP + INP + 72) * 4 + 64;          // ~68 KB
  cudaFuncSetAttribute(enc_kernel, cudaFuncAttributeMaxDynamicSharedMemorySize, enc_smem);
  cudaFuncSetAttribute(dec_kernel, cudaFuncAttributeMaxDynamicSharedMemorySize, dec_smem);

  conv_init_kernel<<<16384, 256>>>(eWhh);
  tr_kernel<<<dim3(256, 15), dim3(32, 8)>>>(eWih);
  gx_kernel<<<dim3(32, 256), 256>>>(x, ebih, ebhh);
  enc_kernel<<<NCTA, 256, enc_smem>>>();
  weff_kernel<<<229, 128>>>(dWih, dWhh, dWhr);
  dec_g0_kernel<<<229, 256>>>(dWih, dbih, dbhh);
  dec_kernel<<<DCTA, 256, dec_smem>>>(dbih, dbhh, out);
  softmax_kernel<<<SEQ, 512>>>(out);
}